// round 6
// baseline (speedup 1.0000x reference)
#include <cuda_runtime.h>

#define N_POINTS    32768
#define EMB         64
#define NUM_CLASSES 50
#define NUM_HOUSES  5
#define NUM_WIN     6            // NUM_WINDOWS + 1 (last = frame)
#define BOXES       (NUM_HOUSES * NUM_WIN)   // 30

// Output: data (N*64) | contains (50*N) | dists (50*30*N)
#define OUT_CONTAINS ((size_t)N_POINTS * EMB)
#define OUT_DISTS    (OUT_CONTAINS + (size_t)NUM_CLASSES * N_POINTS)

typedef unsigned long long u64;

__device__ __forceinline__ u64 f32x2_sub(u64 a, u64 b) {
    u64 r; asm("sub.rn.f32x2 %0, %1, %2;" : "=l"(r) : "l"(a), "l"(b)); return r;
}
__device__ __forceinline__ u64 f32x2_add(u64 a, u64 b) {
    u64 r; asm("add.rn.f32x2 %0, %1, %2;" : "=l"(r) : "l"(a), "l"(b)); return r;
}
__device__ __forceinline__ u64 f32x2_mul(u64 a, u64 b) {
    u64 r; asm("mul.rn.f32x2 %0, %1, %2;" : "=l"(r) : "l"(a), "l"(b)); return r;
}
__device__ __forceinline__ u64 f32x2_fma(u64 a, u64 b, u64 c) {
    u64 r; asm("fma.rn.f32x2 %0, %1, %2, %3;" : "=l"(r) : "l"(a), "l"(b), "l"(c)); return r;
}
__device__ __forceinline__ u64 pack2(float x, float y) {
    u64 r; asm("mov.b64 %0, {%1, %2};" : "=l"(r) : "f"(x), "f"(y)); return r;
}
__device__ __forceinline__ void unpack2(u64 v, float& x, float& y) {
    asm("mov.b64 {%0, %1}, %2;" : "=f"(x), "=f"(y) : "l"(v));
}

// Two points share one box float4: clamp each (scalar FMNMX), packed square.
#define PAIR2_FMA(J, ACC_A, ACC_B) {                              \
    const float4 bb = bx[(J)];                                    \
    float ax, ay, qx, qy;                                         \
    unpack2(p0[(J)], ax, ay);                                     \
    unpack2(p1[(J)], qx, qy);                                     \
    const float ca0 = fminf(fmaxf(ax, bb.x), bb.z);               \
    const float ca1 = fminf(fmaxf(ay, bb.y), bb.w);               \
    const float cb0 = fminf(fmaxf(qx, bb.x), bb.z);               \
    const float cb1 = fminf(fmaxf(qy, bb.y), bb.w);               \
    const u64 da = f32x2_sub(p0[(J)], pack2(ca0, ca1));           \
    const u64 db = f32x2_sub(p1[(J)], pack2(cb0, cb1));           \
    ACC_A = f32x2_fma(da, da, ACC_A);                             \
    ACC_B = f32x2_fma(db, db, ACC_B); }

#define PAIR2_MUL(J, ACC_A, ACC_B) {                              \
    const float4 bb = bx[(J)];                                    \
    float ax, ay, qx, qy;                                         \
    unpack2(p0[(J)], ax, ay);                                     \
    unpack2(p1[(J)], qx, qy);                                     \
    const float ca0 = fminf(fmaxf(ax, bb.x), bb.z);               \
    const float ca1 = fminf(fmaxf(ay, bb.y), bb.w);               \
    const float cb0 = fminf(fmaxf(qx, bb.x), bb.z);               \
    const float cb1 = fminf(fmaxf(qy, bb.y), bb.w);               \
    const u64 da = f32x2_sub(p0[(J)], pack2(ca0, ca1));           \
    const u64 db = f32x2_sub(p1[(J)], pack2(cb0, cb1));           \
    ACC_A = f32x2_mul(da, da);                                    \
    ACC_B = f32x2_mul(db, db); }

#define GRP_STRIDE 9   // 8 data float4 + 1 pad -> 144B group skew (4 banks)

__global__ __launch_bounds__(256, 4)
void geom_kernel(const float* __restrict__ data,
                 const float* __restrict__ shape,   // [50][5][6][2][64]
                 float* __restrict__ out)
{
    // s_box[box][g*9 + slot] = (lo[2j],lo[2j+1],hi[2j],hi[2j+1]), j=g*8+slot.
    // Group stride 9 float4 = 36 words == 4 banks (mod 32): the 4 lane-octets
    // hit disjoint bank quads -> conflict-free broadcast LDS.128.
    __shared__ float4 s_box[BOXES][4 * GRP_STRIDE];

    const int c   = blockIdx.y;
    const int tid = threadIdx.x;

    // ---- stage this class's 30 boxes, min/max-normalized, interleaved ----
    const float2* sb2 = reinterpret_cast<const float2*>(
        shape + (size_t)c * (BOXES * 2 * EMB));
    #pragma unroll
    for (int e = tid; e < BOXES * 32; e += 256) {
        const int box = e >> 5;
        const int j   = e & 31;
        const float2 a = sb2[box * 64 + j];        // corner 0, dims 2j,2j+1
        const float2 b = sb2[box * 64 + 32 + j];   // corner 1
        s_box[box][(j >> 3) * GRP_STRIDE + (j & 7)] =
            make_float4(fminf(a.x, b.x), fminf(a.y, b.y),
                        fmaxf(a.x, b.x), fmaxf(a.y, b.y));
    }

    // ---- data passthrough (class-slice 0 only): linear block copy ----
    if (blockIdx.y == 0) {
        // this block covers 128 points = 8192 floats = 2048 float4
        const float4* src = reinterpret_cast<const float4*>(
            data + (size_t)blockIdx.x * 128 * EMB);
        float4* dst = reinterpret_cast<float4*>(
            out + (size_t)blockIdx.x * 128 * EMB);
        #pragma unroll
        for (int k = 0; k < 8; k++)
            dst[tid + 256 * k] = src[tid + 256 * k];
    }
    __syncthreads();

    // ---- 4 threads per point, 2 points per thread ----
    const int lane = tid & 31;
    const int warp = tid >> 5;
    const int g    = lane >> 3;   // dim group: dims [g*16, g*16+16)
    const int i    = lane & 7;
    const int n0   = blockIdx.x * 128 + warp * 16 + i;   // and n0+8

    // 16 dims per point = 8 packed f32x2, two points
    u64 p0[8], p1[8];
    {
        const ulonglong2* dp0 = reinterpret_cast<const ulonglong2*>(
            data + (size_t)n0 * EMB + g * 16);
        const ulonglong2* dp1 = reinterpret_cast<const ulonglong2*>(
            data + (size_t)(n0 + 8) * EMB + g * 16);
        #pragma unroll
        for (int k = 0; k < 4; k++) {
            const ulonglong2 v0 = dp0[k];
            const ulonglong2 v1 = dp1[k];
            p0[2 * k] = v0.x;  p0[2 * k + 1] = v0.y;
            p1[2 * k] = v1.x;  p1[2 * k + 1] = v1.y;
        }
    }

    float* __restrict__ out_dists = out + OUT_DISTS
                                  + (size_t)c * BOXES * N_POINTS + n0;

    bool town0 = false, town1 = false;
    #pragma unroll 1
    for (int h = 0; h < NUM_HOUSES; h++) {
        bool anyw0 = false, frame0 = false;
        bool anyw1 = false, frame1 = false;
        #pragma unroll 2
        for (int w = 0; w < NUM_WIN; w++) {
            const int box = h * NUM_WIN + w;
            const float4* bx = &s_box[box][g * GRP_STRIDE];
            u64 a0, a1, b0, b1;
            PAIR2_MUL(0, a0, b0)
            PAIR2_MUL(1, a1, b1)
            #pragma unroll
            for (int j = 2; j < 8; j += 2) {
                PAIR2_FMA(j + 0, a0, b0)
                PAIR2_FMA(j + 1, a1, b1)
            }
            const u64 sa = f32x2_add(a0, a1);
            const u64 sb = f32x2_add(b0, b1);
            float x0, y0, x1, y1;
            unpack2(sa, x0, y0);
            unpack2(sb, x1, y1);
            float sq0 = x0 + y0;
            float sq1 = x1 + y1;
            // reduce partials across the 4 dim-groups (lanes xor 8, 16)
            sq0 += __shfl_xor_sync(0xffffffffu, sq0, 8);
            sq0 += __shfl_xor_sync(0xffffffffu, sq0, 16);
            sq1 += __shfl_xor_sync(0xffffffffu, sq1, 8);
            sq1 += __shfl_xor_sync(0xffffffffu, sq1, 16);

            // inside <=> all per-dim deltas 0 <=> sq == 0 (exact; partials >= 0)
            const bool ins0 = (sq0 == 0.0f);
            const bool ins1 = (sq1 == 0.0f);
            if (w < NUM_WIN - 1) { anyw0 |= ins0; anyw1 |= ins1; }
            else                 { frame0 = ins0; frame1 = ins1; }

            if (g == 0) {
                float d0, d1;
                asm("sqrt.approx.f32 %0, %1;" : "=f"(d0) : "f"(sq0));
                asm("sqrt.approx.f32 %0, %1;" : "=f"(d1) : "f"(sq1));
                out_dists[(size_t)box * N_POINTS]     = d0;
                out_dists[(size_t)box * N_POINTS + 8] = d1;
            }
        }
        town0 |= (frame0 && !anyw0);
        town1 |= (frame1 && !anyw1);
    }

    if (g == 0) {
        out[OUT_CONTAINS + (size_t)c * N_POINTS + n0]     = town0 ? 1.0f : 0.0f;
        out[OUT_CONTAINS + (size_t)c * N_POINTS + n0 + 8] = town1 ? 1.0f : 0.0f;
    }
}

extern "C" void kernel_launch(void* const* d_in, const int* in_sizes, int n_in,
                              void* d_out, int out_size) {
    const float* data  = (const float*)d_in[0];
    const float* shape = (const float*)d_in[1];
    float* out = (float*)d_out;

    dim3 grid(N_POINTS / 128, NUM_CLASSES);
    geom_kernel<<<grid, 256>>>(data, shape, out);
}

// round 7
// speedup vs baseline: 1.1762x; 1.1762x over previous
#include <cuda_runtime.h>

#define N_POINTS    32768
#define EMB         64
#define NUM_CLASSES 50
#define NUM_HOUSES  5
#define NUM_WIN     6            // NUM_WINDOWS + 1 (last = frame)
#define BOXES       (NUM_HOUSES * NUM_WIN)   // 30

// Output: data (N*64) | contains (50*N) | dists (50*30*N)
#define OUT_CONTAINS ((size_t)N_POINTS * EMB)
#define OUT_DISTS    (OUT_CONTAINS + (size_t)NUM_CLASSES * N_POINTS)

typedef unsigned long long u64;

__device__ __forceinline__ u64 f32x2_sub(u64 a, u64 b) {
    u64 r; asm("sub.rn.f32x2 %0, %1, %2;" : "=l"(r) : "l"(a), "l"(b)); return r;
}
__device__ __forceinline__ u64 f32x2_add(u64 a, u64 b) {
    u64 r; asm("add.rn.f32x2 %0, %1, %2;" : "=l"(r) : "l"(a), "l"(b)); return r;
}
__device__ __forceinline__ u64 f32x2_mul(u64 a, u64 b) {
    u64 r; asm("mul.rn.f32x2 %0, %1, %2;" : "=l"(r) : "l"(a), "l"(b)); return r;
}
__device__ __forceinline__ u64 f32x2_fma(u64 a, u64 b, u64 c) {
    u64 r; asm("fma.rn.f32x2 %0, %1, %2, %3;" : "=l"(r) : "l"(a), "l"(b), "l"(c)); return r;
}
__device__ __forceinline__ u64 pack2(float x, float y) {
    u64 r; asm("mov.b64 %0, {%1, %2};" : "=l"(r) : "f"(x), "f"(y)); return r;
}
__device__ __forceinline__ void unpack2(u64 v, float& x, float& y) {
    asm("mov.b64 {%0, %1}, %2;" : "=f"(x), "=f"(y) : "l"(v));
}

// One 2-dim step: scalar clamp (FMNMX x4), packed (p-c)^2 accumulate.
#define PAIR_FMA(J, ACC) {                                        \
    const float4 bb = bx[(J)];                                    \
    float px, py; unpack2(p[(J)], px, py);                        \
    const float c0 = fminf(fmaxf(px, bb.x), bb.z);                \
    const float c1 = fminf(fmaxf(py, bb.y), bb.w);                \
    const u64 d = f32x2_sub(p[(J)], pack2(c0, c1));               \
    ACC = f32x2_fma(d, d, ACC); }

#define PAIR_MUL(J, ACC) {                                        \
    const float4 bb = bx[(J)];                                    \
    float px, py; unpack2(p[(J)], px, py);                        \
    const float c0 = fminf(fmaxf(px, bb.x), bb.z);                \
    const float c1 = fminf(fmaxf(py, bb.y), bb.w);                \
    const u64 d = f32x2_sub(p[(J)], pack2(c0, c1));               \
    ACC = f32x2_mul(d, d); }

#define GRP_STRIDE 17  // 16 data float4 + 1 pad -> 272B group skew (4 banks)

__global__ __launch_bounds__(256, 4)
void geom_kernel(const float* __restrict__ data,
                 const float* __restrict__ shape,   // [50][5][6][2][64]
                 float* __restrict__ out)
{
    // s_box[box][g*17 + slot] = (lo[2j],lo[2j+1],hi[2j],hi[2j+1]),
    // j = g*16 + slot. Half-warp broadcast addresses differ by 68 words
    // == 4 banks (mod 32) -> disjoint bank quads, conflict-free LDS.128.
    __shared__ float4 s_box[BOXES][2 * GRP_STRIDE];

    const int c   = blockIdx.y;
    const int tid = threadIdx.x;

    // ---- stage this class's 30 boxes, min/max-normalized, interleaved ----
    const float2* sb2 = reinterpret_cast<const float2*>(
        shape + (size_t)c * (BOXES * 2 * EMB));
    #pragma unroll
    for (int e = tid; e < BOXES * 32; e += 256) {
        const int box = e >> 5;
        const int j   = e & 31;
        const float2 a = sb2[box * 64 + j];        // corner 0, dims 2j,2j+1
        const float2 b = sb2[box * 64 + 32 + j];   // corner 1
        s_box[box][(j >> 4) * GRP_STRIDE + (j & 15)] =
            make_float4(fminf(a.x, b.x), fminf(a.y, b.y),
                        fmaxf(a.x, b.x), fmaxf(a.y, b.y));
    }

    // ---- data passthrough (class-slice 0 only): linear block copy ----
    if (blockIdx.y == 0) {
        // this block covers 128 points = 8192 floats = 2048 float4
        const float4* src = reinterpret_cast<const float4*>(
            data + (size_t)blockIdx.x * 128 * EMB);
        float4* dst = reinterpret_cast<float4*>(
            out + (size_t)blockIdx.x * 128 * EMB);
        #pragma unroll
        for (int k = 0; k < 8; k++)
            dst[tid + 256 * k] = src[tid + 256 * k];
    }
    __syncthreads();

    // ---- 2 threads per point: lane = g*16 + i ----
    const int lane = tid & 31;
    const int warp = tid >> 5;
    const int g    = lane >> 4;   // dim group: dims [g*32, g*32+32)
    const int i    = lane & 15;   // point within warp's 16
    const int n    = blockIdx.x * 128 + warp * 16 + i;

    // 32 dims = 16 packed f32x2
    u64 p[16];
    const ulonglong2* dp = reinterpret_cast<const ulonglong2*>(
        data + (size_t)n * EMB + g * 32);
    #pragma unroll
    for (int k = 0; k < 8; k++) {
        const ulonglong2 v = dp[k];
        p[2 * k]     = v.x;
        p[2 * k + 1] = v.y;
    }

    float* __restrict__ out_dists = out + OUT_DISTS
                                  + (size_t)c * BOXES * N_POINTS + n;

    bool town = false;
    #pragma unroll 1
    for (int h = 0; h < NUM_HOUSES; h++) {
        bool anyw = false, frame = false;
        #pragma unroll
        for (int w = 0; w < NUM_WIN; w++) {
            const int box = h * NUM_WIN + w;
            const float4* bx = &s_box[box][g * GRP_STRIDE];
            u64 a0, a1;
            PAIR_MUL(0, a0) PAIR_MUL(1, a1)
            #pragma unroll
            for (int j = 2; j < 16; j += 2) {
                PAIR_FMA(j + 0, a0)
                PAIR_FMA(j + 1, a1)
            }
            const u64 s = f32x2_add(a0, a1);
            float sx, sy; unpack2(s, sx, sy);
            float sq = sx + sy;
            // combine the two 32-dim halves (lanes xor 16)
            sq += __shfl_xor_sync(0xffffffffu, sq, 16);

            // inside <=> clamped == p in every dim <=> sq == 0 (exact;
            // both partials >= 0, so total 0 iff both are 0)
            const bool ins = (sq == 0.0f);
            if (w < NUM_WIN - 1) anyw |= ins;
            else                 frame = ins;

            if (g == 0) {
                float dist;
                asm("sqrt.approx.f32 %0, %1;" : "=f"(dist) : "f"(sq));
                out_dists[(size_t)box * N_POINTS] = dist;
            }
        }
        town |= (frame && !anyw);
    }

    if (g == 0)
        out[OUT_CONTAINS + (size_t)c * N_POINTS + n] = town ? 1.0f : 0.0f;
}

extern "C" void kernel_launch(void* const* d_in, const int* in_sizes, int n_in,
                              void* d_out, int out_size) {
    const float* data  = (const float*)d_in[0];
    const float* shape = (const float*)d_in[1];
    float* out = (float*)d_out;

    dim3 grid(N_POINTS / 128, NUM_CLASSES);
    geom_kernel<<<grid, 256>>>(data, shape, out);
}

// round 8
// speedup vs baseline: 1.1768x; 1.0006x over previous
#include <cuda_runtime.h>

#define N_POINTS    32768
#define EMB         64
#define NUM_CLASSES 50
#define NUM_HOUSES  5
#define NUM_WIN     6            // NUM_WINDOWS + 1 (last = frame)
#define BOXES       (NUM_HOUSES * NUM_WIN)   // 30

// Output: data (N*64) | contains (50*N) | dists (50*30*N)
#define OUT_CONTAINS ((size_t)N_POINTS * EMB)
#define OUT_DISTS    (OUT_CONTAINS + (size_t)NUM_CLASSES * N_POINTS)

typedef unsigned long long u64;

__device__ __forceinline__ u64 f32x2_sub(u64 a, u64 b) {
    u64 r; asm("sub.rn.f32x2 %0, %1, %2;" : "=l"(r) : "l"(a), "l"(b)); return r;
}
__device__ __forceinline__ u64 f32x2_add(u64 a, u64 b) {
    u64 r; asm("add.rn.f32x2 %0, %1, %2;" : "=l"(r) : "l"(a), "l"(b)); return r;
}
__device__ __forceinline__ u64 f32x2_mul(u64 a, u64 b) {
    u64 r; asm("mul.rn.f32x2 %0, %1, %2;" : "=l"(r) : "l"(a), "l"(b)); return r;
}
__device__ __forceinline__ u64 f32x2_fma(u64 a, u64 b, u64 c) {
    u64 r; asm("fma.rn.f32x2 %0, %1, %2, %3;" : "=l"(r) : "l"(a), "l"(b), "l"(c)); return r;
}
__device__ __forceinline__ u64 pack2(float x, float y) {
    u64 r; asm("mov.b64 %0, {%1, %2};" : "=l"(r) : "f"(x), "f"(y)); return r;
}
__device__ __forceinline__ void unpack2(u64 v, float& x, float& y) {
    asm("mov.b64 {%0, %1}, %2;" : "=f"(x), "=f"(y) : "l"(v));
}

// Two points share one box float4 (one LDS): clamp each point scalar
// (FMNMX), packed (p-c)^2 accumulate into separate chains.
#define PAIR2_FMA(J, ACC_A, ACC_B) {                              \
    const float4 bb = bx[(J)];                                    \
    float ax, ay, qx, qy;                                         \
    unpack2(p0[(J)], ax, ay);                                     \
    unpack2(p1[(J)], qx, qy);                                     \
    const float ca0 = fminf(fmaxf(ax, bb.x), bb.z);               \
    const float ca1 = fminf(fmaxf(ay, bb.y), bb.w);               \
    const float cb0 = fminf(fmaxf(qx, bb.x), bb.z);               \
    const float cb1 = fminf(fmaxf(qy, bb.y), bb.w);               \
    const u64 da = f32x2_sub(p0[(J)], pack2(ca0, ca1));           \
    const u64 db = f32x2_sub(p1[(J)], pack2(cb0, cb1));           \
    ACC_A = f32x2_fma(da, da, ACC_A);                             \
    ACC_B = f32x2_fma(db, db, ACC_B); }

#define PAIR2_MUL(J, ACC_A, ACC_B) {                              \
    const float4 bb = bx[(J)];                                    \
    float ax, ay, qx, qy;                                         \
    unpack2(p0[(J)], ax, ay);                                     \
    unpack2(p1[(J)], qx, qy);                                     \
    const float ca0 = fminf(fmaxf(ax, bb.x), bb.z);               \
    const float ca1 = fminf(fmaxf(ay, bb.y), bb.w);               \
    const float cb0 = fminf(fmaxf(qx, bb.x), bb.z);               \
    const float cb1 = fminf(fmaxf(qy, bb.y), bb.w);               \
    const u64 da = f32x2_sub(p0[(J)], pack2(ca0, ca1));           \
    const u64 db = f32x2_sub(p1[(J)], pack2(cb0, cb1));           \
    ACC_A = f32x2_mul(da, da);                                    \
    ACC_B = f32x2_mul(db, db); }

#define GRP_STRIDE 17  // 16 data float4 + 1 pad -> 272B group skew (4 banks)

__global__ __launch_bounds__(256, 2)
void geom_kernel(const float* __restrict__ data,
                 const float* __restrict__ shape,   // [50][5][6][2][64]
                 float* __restrict__ out)
{
    // s_box[box][g*17 + slot] = (lo[2j],lo[2j+1],hi[2j],hi[2j+1]),
    // j = g*16 + slot. Half-warp broadcast addresses differ by 68 words
    // == 4 banks (mod 32) -> disjoint bank quads, conflict-free LDS.128.
    __shared__ float4 s_box[BOXES][2 * GRP_STRIDE];

    const int c   = blockIdx.y;
    const int tid = threadIdx.x;

    // ---- stage this class's 30 boxes, min/max-normalized, interleaved ----
    const float2* sb2 = reinterpret_cast<const float2*>(
        shape + (size_t)c * (BOXES * 2 * EMB));
    #pragma unroll
    for (int e = tid; e < BOXES * 32; e += 256) {
        const int box = e >> 5;
        const int j   = e & 31;
        const float2 a = sb2[box * 64 + j];        // corner 0, dims 2j,2j+1
        const float2 b = sb2[box * 64 + 32 + j];   // corner 1
        s_box[box][(j >> 4) * GRP_STRIDE + (j & 15)] =
            make_float4(fminf(a.x, b.x), fminf(a.y, b.y),
                        fmaxf(a.x, b.x), fmaxf(a.y, b.y));
    }

    // ---- data passthrough (class-slice 0 only): linear block copy ----
    if (blockIdx.y == 0) {
        // this block covers 256 points = 16384 floats = 4096 float4
        const float4* src = reinterpret_cast<const float4*>(
            data + (size_t)blockIdx.x * 256 * EMB);
        float4* dst = reinterpret_cast<float4*>(
            out + (size_t)blockIdx.x * 256 * EMB);
        #pragma unroll
        for (int k = 0; k < 16; k++)
            dst[tid + 256 * k] = src[tid + 256 * k];
    }
    __syncthreads();

    // ---- 2 threads per point, 2 points per thread: 32 points/warp ----
    const int lane = tid & 31;
    const int warp = tid >> 5;
    const int g    = lane >> 4;   // dim group: dims [g*32, g*32+32)
    const int i    = lane & 15;
    const int n0   = blockIdx.x * 256 + warp * 32 + i;   // and n0+16

    // 32 dims per point = 16 packed f32x2, two points
    u64 p0[16], p1[16];
    {
        const ulonglong2* dp0 = reinterpret_cast<const ulonglong2*>(
            data + (size_t)n0 * EMB + g * 32);
        const ulonglong2* dp1 = reinterpret_cast<const ulonglong2*>(
            data + (size_t)(n0 + 16) * EMB + g * 32);
        #pragma unroll
        for (int k = 0; k < 8; k++) {
            const ulonglong2 v0 = dp0[k];
            const ulonglong2 v1 = dp1[k];
            p0[2 * k] = v0.x;  p0[2 * k + 1] = v0.y;
            p1[2 * k] = v1.x;  p1[2 * k + 1] = v1.y;
        }
    }

    float* __restrict__ out_dists = out + OUT_DISTS
                                  + (size_t)c * BOXES * N_POINTS + n0;

    bool town0 = false, town1 = false;
    #pragma unroll 1
    for (int h = 0; h < NUM_HOUSES; h++) {
        bool anyw0 = false, frame0 = false;
        bool anyw1 = false, frame1 = false;
        #pragma unroll 2
        for (int w = 0; w < NUM_WIN; w++) {
            const int box = h * NUM_WIN + w;
            const float4* bx = &s_box[box][g * GRP_STRIDE];
            u64 a0, a1, b0, b1;
            PAIR2_MUL(0, a0, b0)
            PAIR2_MUL(1, a1, b1)
            #pragma unroll
            for (int j = 2; j < 16; j += 2) {
                PAIR2_FMA(j + 0, a0, b0)
                PAIR2_FMA(j + 1, a1, b1)
            }
            const u64 sa = f32x2_add(a0, a1);
            const u64 sb = f32x2_add(b0, b1);
            float x0, y0, x1, y1;
            unpack2(sa, x0, y0);
            unpack2(sb, x1, y1);
            float sq0 = x0 + y0;
            float sq1 = x1 + y1;
            // combine the two 32-dim halves (lanes xor 16); one shfl per point
            sq0 += __shfl_xor_sync(0xffffffffu, sq0, 16);
            sq1 += __shfl_xor_sync(0xffffffffu, sq1, 16);

            // inside <=> clamped == p in every dim <=> sq == 0 (exact;
            // both partials >= 0, so total 0 iff both are 0)
            const bool ins0 = (sq0 == 0.0f);
            const bool ins1 = (sq1 == 0.0f);
            if (w < NUM_WIN - 1) { anyw0 |= ins0; anyw1 |= ins1; }
            else                 { frame0 = ins0; frame1 = ins1; }

            if (g == 0) {
                float d0, d1;
                asm("sqrt.approx.f32 %0, %1;" : "=f"(d0) : "f"(sq0));
                asm("sqrt.approx.f32 %0, %1;" : "=f"(d1) : "f"(sq1));
                out_dists[(size_t)box * N_POINTS]      = d0;
                out_dists[(size_t)box * N_POINTS + 16] = d1;
            }
        }
        town0 |= (frame0 && !anyw0);
        town1 |= (frame1 && !anyw1);
    }

    if (g == 0) {
        out[OUT_CONTAINS + (size_t)c * N_POINTS + n0]      = town0 ? 1.0f : 0.0f;
        out[OUT_CONTAINS + (size_t)c * N_POINTS + n0 + 16] = town1 ? 1.0f : 0.0f;
    }
}

extern "C" void kernel_launch(void* const* d_in, const int* in_sizes, int n_in,
                              void* d_out, int out_size) {
    const float* data  = (const float*)d_in[0];
    const float* shape = (const float*)d_in[1];
    float* out = (float*)d_out;

    dim3 grid(N_POINTS / 256, NUM_CLASSES);
    geom_kernel<<<grid, 256>>>(data, shape, out);
}

// round 10
// speedup vs baseline: 1.2489x; 1.0612x over previous
#include <cuda_runtime.h>

#define N_POINTS    32768
#define EMB         64
#define NUM_CLASSES 50
#define NUM_HOUSES  5
#define NUM_WIN     6            // NUM_WINDOWS + 1 (last = frame)
#define BOXES       (NUM_HOUSES * NUM_WIN)   // 30

// Output: data (N*64) | contains (50*N) | dists (50*30*N)
#define OUT_CONTAINS ((size_t)N_POINTS * EMB)
#define OUT_DISTS    (OUT_CONTAINS + (size_t)NUM_CLASSES * N_POINTS)

typedef unsigned long long u64;

__device__ __forceinline__ u64 f32x2_sub(u64 a, u64 b) {
    u64 r; asm("sub.rn.f32x2 %0, %1, %2;" : "=l"(r) : "l"(a), "l"(b)); return r;
}
__device__ __forceinline__ u64 f32x2_add(u64 a, u64 b) {
    u64 r; asm("add.rn.f32x2 %0, %1, %2;" : "=l"(r) : "l"(a), "l"(b)); return r;
}
__device__ __forceinline__ u64 f32x2_mul(u64 a, u64 b) {
    u64 r; asm("mul.rn.f32x2 %0, %1, %2;" : "=l"(r) : "l"(a), "l"(b)); return r;
}
__device__ __forceinline__ u64 f32x2_fma(u64 a, u64 b, u64 c) {
    u64 r; asm("fma.rn.f32x2 %0, %1, %2, %3;" : "=l"(r) : "l"(a), "l"(b), "l"(c)); return r;
}
__device__ __forceinline__ u64 pack2(float x, float y) {
    u64 r; asm("mov.b64 %0, {%1, %2};" : "=l"(r) : "f"(x), "f"(y)); return r;
}
__device__ __forceinline__ void unpack2(u64 v, float& x, float& y) {
    asm("mov.b64 {%0, %1}, %2;" : "=f"(x), "=f"(y) : "l"(v));
}

// Route A (clamp form): bb = (lo0,lo1,hi0,hi1). 4 FMNMX (alu) + sub/fma (fma).
#define PAIRA_FMA(J, ACC) {                                       \
    const ulonglong2 bb = bx[(J)];                                \
    float lo0, lo1, hi0, hi1, px, py;                             \
    unpack2(bb.x, lo0, lo1); unpack2(bb.y, hi0, hi1);             \
    unpack2(p[(J)], px, py);                                      \
    const float c0 = fminf(fmaxf(px, lo0), hi0);                  \
    const float c1 = fminf(fmaxf(py, lo1), hi1);                  \
    const u64 d = f32x2_sub(p[(J)], pack2(c0, c1));               \
    ACC = f32x2_fma(d, d, ACC); }

#define PAIRA_MUL(J, ACC) {                                       \
    const ulonglong2 bb = bx[(J)];                                \
    float lo0, lo1, hi0, hi1, px, py;                             \
    unpack2(bb.x, lo0, lo1); unpack2(bb.y, hi0, hi1);             \
    unpack2(p[(J)], px, py);                                      \
    const float c0 = fminf(fmaxf(px, lo0), hi0);                  \
    const float c1 = fminf(fmaxf(py, lo1), hi1);                  \
    const u64 d = f32x2_sub(p[(J)], pack2(c0, c1));               \
    ACC = f32x2_mul(d, d); }

// Route C (center form): bb = (ctr0,ctr1,hw0,hw1).
// packed sub (fma) + 2x FADD |t|-hw (fma, abs folded) + 2x FMNMX (alu) + fma.
#define PAIRC_FMA(J, ACC) {                                       \
    const ulonglong2 bb = bx[(J)];                                \
    const u64 t = f32x2_sub(p[(J)], bb.x);                        \
    float tx, ty, h0, h1;                                         \
    unpack2(t, tx, ty); unpack2(bb.y, h0, h1);                    \
    const float a0_ = fabsf(tx) - h0;                             \
    const float a1_ = fabsf(ty) - h1;                             \
    const float d0 = fmaxf(a0_, 0.0f);                            \
    const float d1 = fmaxf(a1_, 0.0f);                            \
    const u64 d = pack2(d0, d1);                                  \
    ACC = f32x2_fma(d, d, ACC); }

#define PAIRC_MUL(J, ACC) {                                       \
    const ulonglong2 bb = bx[(J)];                                \
    const u64 t = f32x2_sub(p[(J)], bb.x);                        \
    float tx, ty, h0, h1;                                         \
    unpack2(t, tx, ty); unpack2(bb.y, h0, h1);                    \
    const float a0_ = fabsf(tx) - h0;                             \
    const float a1_ = fabsf(ty) - h1;                             \
    const float d0 = fmaxf(a0_, 0.0f);                            \
    const float d1 = fmaxf(a1_, 0.0f);                            \
    const u64 d = pack2(d0, d1);                                  \
    ACC = f32x2_mul(d, d); }

#define GRP_STRIDE 17  // 16 data float4 + 1 pad -> 272B group skew (4 banks)

__global__ __launch_bounds__(256, 3)
void geom_kernel(const float* __restrict__ data,
                 const float* __restrict__ shape,   // [50][5][6][2][64]
                 float* __restrict__ out)
{
    // s_box[box][g*17 + slot]: even slot -> (lo0,lo1,hi0,hi1)  [route A]
    //                          odd  slot -> (ctr0,ctr1,hw0,hw1) [route C]
    // Half-warp broadcast addresses differ by 68 words == 4 banks (mod 32)
    // -> disjoint bank quads, conflict-free LDS.128.
    __shared__ float4 s_box[BOXES][2 * GRP_STRIDE];

    const int c   = blockIdx.y;
    const int tid = threadIdx.x;

    // ---- stage this class's 30 boxes ----
    const float2* sb2 = reinterpret_cast<const float2*>(
        shape + (size_t)c * (BOXES * 2 * EMB));
    #pragma unroll
    for (int e = tid; e < BOXES * 32; e += 256) {
        const int box = e >> 5;
        const int j   = e & 31;                    // pair = dims 2j, 2j+1
        const float2 a = sb2[box * 64 + j];        // corner 0
        const float2 b = sb2[box * 64 + 32 + j];   // corner 1
        const float lo0 = fminf(a.x, b.x), hi0 = fmaxf(a.x, b.x);
        const float lo1 = fminf(a.y, b.y), hi1 = fmaxf(a.y, b.y);
        float4 v;
        if (j & 1)   // route C slot
            v = make_float4(0.5f * (lo0 + hi0), 0.5f * (lo1 + hi1),
                            0.5f * (hi0 - lo0), 0.5f * (hi1 - lo1));
        else         // route A slot
            v = make_float4(lo0, lo1, hi0, hi1);
        s_box[box][(j >> 4) * GRP_STRIDE + (j & 15)] = v;
    }

    // ---- data passthrough (class-slice 0 only): linear block copy ----
    if (blockIdx.y == 0) {
        // this block covers 128 points = 8192 floats = 2048 float4
        const float4* src = reinterpret_cast<const float4*>(
            data + (size_t)blockIdx.x * 128 * EMB);
        float4* dst = reinterpret_cast<float4*>(
            out + (size_t)blockIdx.x * 128 * EMB);
        #pragma unroll
        for (int k = 0; k < 8; k++)
            dst[tid + 256 * k] = src[tid + 256 * k];
    }
    __syncthreads();

    // ---- 2 threads per point: lane = g*16 + i ----
    const int lane = tid & 31;
    const int warp = tid >> 5;
    const int g    = lane >> 4;   // dim group: dims [g*32, g*32+32)
    const int i    = lane & 15;   // point within warp's 16
    const int n    = blockIdx.x * 128 + warp * 16 + i;

    // 32 dims = 16 packed f32x2
    u64 p[16];
    const ulonglong2* dp = reinterpret_cast<const ulonglong2*>(
        data + (size_t)n * EMB + g * 32);
    #pragma unroll
    for (int k = 0; k < 8; k++) {
        const ulonglong2 v = dp[k];
        p[2 * k]     = v.x;
        p[2 * k + 1] = v.y;
    }

    float* __restrict__ out_dists = out + OUT_DISTS
                                  + (size_t)c * BOXES * N_POINTS + n;

    bool town = false;
    #pragma unroll 1
    for (int h = 0; h < NUM_HOUSES; h++) {
        bool anyw = false, frame = false;
        #pragma unroll
        for (int w = 0; w < NUM_WIN; w++) {
            const int box = h * NUM_WIN + w;
            const ulonglong2* bx = reinterpret_cast<const ulonglong2*>(
                &s_box[box][g * GRP_STRIDE]);
            u64 a0, a1, a2, a3;
            // even slots: route A (alu-heavy); odd slots: route C (fma-heavy)
            PAIRA_MUL(0, a0) PAIRC_MUL(1, a1) PAIRA_MUL(2, a2) PAIRC_MUL(3, a3)
            #pragma unroll
            for (int j = 4; j < 16; j += 4) {
                PAIRA_FMA(j + 0, a0)
                PAIRC_FMA(j + 1, a1)
                PAIRA_FMA(j + 2, a2)
                PAIRC_FMA(j + 3, a3)
            }
            const u64 s = f32x2_add(f32x2_add(a0, a1), f32x2_add(a2, a3));
            float sx, sy; unpack2(s, sx, sy);
            float sq = sx + sy;
            // combine the two 32-dim halves (lanes xor 16)
            sq += __shfl_xor_sync(0xffffffffu, sq, 16);

            // inside <=> all per-dim deltas 0 <=> sq == 0 (partials >= 0)
            const bool ins = (sq == 0.0f);
            if (w < NUM_WIN - 1) anyw |= ins;
            else                 frame = ins;

            if (g == 0) {
                float dist;
                asm("sqrt.approx.f32 %0, %1;" : "=f"(dist) : "f"(sq));
                out_dists[(size_t)box * N_POINTS] = dist;
            }
        }
        town |= (frame && !anyw);
    }

    if (g == 0)
        out[OUT_CONTAINS + (size_t)c * N_POINTS + n] = town ? 1.0f : 0.0f;
}

extern "C" void kernel_launch(void* const* d_in, const int* in_sizes, int n_in,
                              void* d_out, int out_size) {
    const float* data  = (const float*)d_in[0];
    const float* shape = (const float*)d_in[1];
    float* out = (float*)d_out;

    dim3 grid(N_POINTS / 128, NUM_CLASSES);
    geom_kernel<<<grid, 256>>>(data, shape, out);
}

// round 11
// speedup vs baseline: 1.3026x; 1.0431x over previous
#include <cuda_runtime.h>

#define N_POINTS    32768
#define EMB         64
#define NUM_CLASSES 50
#define NUM_HOUSES  5
#define NUM_WIN     6            // NUM_WINDOWS + 1 (last = frame)
#define BOXES       (NUM_HOUSES * NUM_WIN)   // 30

// Output: data (N*64) | contains (50*N) | dists (50*30*N)
#define OUT_CONTAINS ((size_t)N_POINTS * EMB)
#define OUT_DISTS    (OUT_CONTAINS + (size_t)NUM_CLASSES * N_POINTS)

typedef unsigned long long u64;

__device__ __forceinline__ u64 f32x2_sub(u64 a, u64 b) {
    u64 r; asm("sub.rn.f32x2 %0, %1, %2;" : "=l"(r) : "l"(a), "l"(b)); return r;
}
__device__ __forceinline__ u64 f32x2_add(u64 a, u64 b) {
    u64 r; asm("add.rn.f32x2 %0, %1, %2;" : "=l"(r) : "l"(a), "l"(b)); return r;
}
__device__ __forceinline__ u64 f32x2_mul(u64 a, u64 b) {
    u64 r; asm("mul.rn.f32x2 %0, %1, %2;" : "=l"(r) : "l"(a), "l"(b)); return r;
}
__device__ __forceinline__ u64 f32x2_fma(u64 a, u64 b, u64 c) {
    u64 r; asm("fma.rn.f32x2 %0, %1, %2, %3;" : "=l"(r) : "l"(a), "l"(b), "l"(c)); return r;
}
__device__ __forceinline__ u64 pack2(float x, float y) {
    u64 r; asm("mov.b64 %0, {%1, %2};" : "=l"(r) : "f"(x), "f"(y)); return r;
}
__device__ __forceinline__ void unpack2(u64 v, float& x, float& y) {
    asm("mov.b64 {%0, %1}, %2;" : "=f"(x), "=f"(y) : "l"(v));
}

// Route A (clamp form), 2 points sharing one box LDS.
// bb = (lo0,lo1,hi0,hi1).
#define PAIRA2(J, ACC_A, ACC_B, OP_A, OP_B) {                     \
    const ulonglong2 bb = bx[(J)];                                \
    float lo0, lo1, hi0, hi1;                                     \
    unpack2(bb.x, lo0, lo1); unpack2(bb.y, hi0, hi1);             \
    float ax, ay, qx, qy;                                         \
    unpack2(p0[(J)], ax, ay); unpack2(p1[(J)], qx, qy);           \
    const float ca0 = fminf(fmaxf(ax, lo0), hi0);                 \
    const float ca1 = fminf(fmaxf(ay, lo1), hi1);                 \
    const float cb0 = fminf(fmaxf(qx, lo0), hi0);                 \
    const float cb1 = fminf(fmaxf(qy, lo1), hi1);                 \
    const u64 da = f32x2_sub(p0[(J)], pack2(ca0, ca1));           \
    const u64 db = f32x2_sub(p1[(J)], pack2(cb0, cb1));           \
    ACC_A = OP_A; ACC_B = OP_B; }

#define PAIRA2_FMA(J, A, B) PAIRA2(J, A, B, f32x2_fma(da,da,A), f32x2_fma(db,db,B))
#define PAIRA2_MUL(J, A, B) PAIRA2(J, A, B, f32x2_mul(da,da),   f32x2_mul(db,db))

// Route C (center form), 2 points sharing one box LDS.
// bb = (ctr0,ctr1,hw0,hw1).
#define PAIRC2(J, ACC_A, ACC_B, OP_A, OP_B) {                     \
    const ulonglong2 bb = bx[(J)];                                \
    float h0, h1; unpack2(bb.y, h0, h1);                          \
    const u64 ta = f32x2_sub(p0[(J)], bb.x);                      \
    const u64 tb = f32x2_sub(p1[(J)], bb.x);                      \
    float tax, tay, tbx, tby;                                     \
    unpack2(ta, tax, tay); unpack2(tb, tbx, tby);                 \
    const float da0 = fmaxf(fabsf(tax) - h0, 0.0f);               \
    const float da1 = fmaxf(fabsf(tay) - h1, 0.0f);               \
    const float db0 = fmaxf(fabsf(tbx) - h0, 0.0f);               \
    const float db1 = fmaxf(fabsf(tby) - h1, 0.0f);               \
    const u64 da = pack2(da0, da1);                               \
    const u64 db = pack2(db0, db1);                               \
    ACC_A = OP_A; ACC_B = OP_B; }

#define PAIRC2_FMA(J, A, B) PAIRC2(J, A, B, f32x2_fma(da,da,A), f32x2_fma(db,db,B))
#define PAIRC2_MUL(J, A, B) PAIRC2(J, A, B, f32x2_mul(da,da),   f32x2_mul(db,db))

#define GRP_STRIDE 17  // 16 data float4 + 1 pad -> 272B group skew (4 banks)

__global__ __launch_bounds__(256, 2)
void geom_kernel(const float* __restrict__ data,
                 const float* __restrict__ shape,   // [50][5][6][2][64]
                 float* __restrict__ out)
{
    // s_box[box][g*17 + slot]: even slot -> (lo0,lo1,hi0,hi1)   [route A]
    //                          odd  slot -> (ctr0,ctr1,hw0,hw1)  [route C]
    // Half-warp broadcast addresses differ by 68 words == 4 banks (mod 32)
    // -> disjoint bank quads, conflict-free LDS.128.
    __shared__ float4 s_box[BOXES][2 * GRP_STRIDE];

    const int c   = blockIdx.y;
    const int tid = threadIdx.x;

    // ---- stage this class's 30 boxes ----
    const float2* sb2 = reinterpret_cast<const float2*>(
        shape + (size_t)c * (BOXES * 2 * EMB));
    #pragma unroll
    for (int e = tid; e < BOXES * 32; e += 256) {
        const int box = e >> 5;
        const int j   = e & 31;                    // pair = dims 2j, 2j+1
        const float2 a = sb2[box * 64 + j];        // corner 0
        const float2 b = sb2[box * 64 + 32 + j];   // corner 1
        const float lo0 = fminf(a.x, b.x), hi0 = fmaxf(a.x, b.x);
        const float lo1 = fminf(a.y, b.y), hi1 = fmaxf(a.y, b.y);
        float4 v;
        if (j & 1)   // route C slot
            v = make_float4(0.5f * (lo0 + hi0), 0.5f * (lo1 + hi1),
                            0.5f * (hi0 - lo0), 0.5f * (hi1 - lo1));
        else         // route A slot
            v = make_float4(lo0, lo1, hi0, hi1);
        s_box[box][(j >> 4) * GRP_STRIDE + (j & 15)] = v;
    }

    // ---- data passthrough (class-slice 0 only): linear block copy ----
    if (blockIdx.y == 0) {
        // this block covers 256 points = 16384 floats = 4096 float4
        const float4* src = reinterpret_cast<const float4*>(
            data + (size_t)blockIdx.x * 256 * EMB);
        float4* dst = reinterpret_cast<float4*>(
            out + (size_t)blockIdx.x * 256 * EMB);
        #pragma unroll
        for (int k = 0; k < 16; k++)
            dst[tid + 256 * k] = src[tid + 256 * k];
    }
    __syncthreads();

    // ---- 2 threads per point, 2 points per thread: 32 points/warp ----
    const int lane = tid & 31;
    const int warp = tid >> 5;
    const int g    = lane >> 4;   // dim group: dims [g*32, g*32+32)
    const int i    = lane & 15;
    const int n0   = blockIdx.x * 256 + warp * 32 + i;   // and n0+16

    // 32 dims per point = 16 packed f32x2, two points
    u64 p0[16], p1[16];
    {
        const ulonglong2* dp0 = reinterpret_cast<const ulonglong2*>(
            data + (size_t)n0 * EMB + g * 32);
        const ulonglong2* dp1 = reinterpret_cast<const ulonglong2*>(
            data + (size_t)(n0 + 16) * EMB + g * 32);
        #pragma unroll
        for (int k = 0; k < 8; k++) {
            const ulonglong2 v0 = dp0[k];
            const ulonglong2 v1 = dp1[k];
            p0[2 * k] = v0.x;  p0[2 * k + 1] = v0.y;
            p1[2 * k] = v1.x;  p1[2 * k + 1] = v1.y;
        }
    }

    float* __restrict__ out_dists = out + OUT_DISTS
                                  + (size_t)c * BOXES * N_POINTS + n0;

    bool town0 = false, town1 = false;
    #pragma unroll 1
    for (int h = 0; h < NUM_HOUSES; h++) {
        bool anyw0 = false, frame0 = false;
        bool anyw1 = false, frame1 = false;
        #pragma unroll 2
        for (int w = 0; w < NUM_WIN; w++) {
            const int box = h * NUM_WIN + w;
            const ulonglong2* bx = reinterpret_cast<const ulonglong2*>(
                &s_box[box][g * GRP_STRIDE]);
            u64 a0, a1, b0, b1;
            // even slots: route A (alu-heavy); odd: route C (fma-heavy)
            PAIRA2_MUL(0, a0, b0)
            PAIRC2_MUL(1, a1, b1)
            #pragma unroll
            for (int j = 2; j < 16; j += 2) {
                PAIRA2_FMA(j + 0, a0, b0)
                PAIRC2_FMA(j + 1, a1, b1)
            }
            const u64 sa = f32x2_add(a0, a1);
            const u64 sb = f32x2_add(b0, b1);
            float x0, y0, x1, y1;
            unpack2(sa, x0, y0);
            unpack2(sb, x1, y1);
            float sq0 = x0 + y0;
            float sq1 = x1 + y1;
            // combine the two 32-dim halves (lanes xor 16); 1 shfl per point
            sq0 += __shfl_xor_sync(0xffffffffu, sq0, 16);
            sq1 += __shfl_xor_sync(0xffffffffu, sq1, 16);

            // inside <=> all per-dim deltas 0 <=> sq == 0 (partials >= 0)
            const bool ins0 = (sq0 == 0.0f);
            const bool ins1 = (sq1 == 0.0f);
            if (w < NUM_WIN - 1) { anyw0 |= ins0; anyw1 |= ins1; }
            else                 { frame0 = ins0; frame1 = ins1; }

            if (g == 0) {
                float d0, d1;
                asm("sqrt.approx.f32 %0, %1;" : "=f"(d0) : "f"(sq0));
                asm("sqrt.approx.f32 %0, %1;" : "=f"(d1) : "f"(sq1));
                out_dists[(size_t)box * N_POINTS]      = d0;
                out_dists[(size_t)box * N_POINTS + 16] = d1;
            }
        }
        town0 |= (frame0 && !anyw0);
        town1 |= (frame1 && !anyw1);
    }

    if (g == 0) {
        out[OUT_CONTAINS + (size_t)c * N_POINTS + n0]      = town0 ? 1.0f : 0.0f;
        out[OUT_CONTAINS + (size_t)c * N_POINTS + n0 + 16] = town1 ? 1.0f : 0.0f;
    }
}

extern "C" void kernel_launch(void* const* d_in, const int* in_sizes, int n_in,
                              void* d_out, int out_size) {
    const float* data  = (const float*)d_in[0];
    const float* shape = (const float*)d_in[1];
    float* out = (float*)d_out;

    dim3 grid(N_POINTS / 256, NUM_CLASSES);
    geom_kernel<<<grid, 256>>>(data, shape, out);
}